// round 1
// baseline (speedup 1.0000x reference)
#include <cuda_runtime.h>
#include <math.h>

#define BATCH 64
#define SEQ   512
#define EMB   192
#define NHEAD 6
#define HD    32
#define MROWS (BATCH * SEQ)   // 32768

// -------- scratch (device globals; no runtime allocation) --------
__device__ float g_x   [BATCH * SEQ * EMB];   // residual stream
__device__ float g_xn  [BATCH * SEQ * EMB];   // LN output
__device__ float g_big [BATCH * SEQ * 768];   // qkv (576 used) / mlp hidden (768)
__device__ float g_attn[BATCH * SEQ * EMB];   // attention head-merged output

// ---------------------------------------------------------------
// input transpose: image [B, C, H, W] -> x [B, S=W*H, C], token t = w*8 + h
// ---------------------------------------------------------------
__global__ void k_tin(const float* __restrict__ img) {
    int idx = blockIdx.x * 256 + threadIdx.x;
    if (idx >= BATCH * SEQ * EMB) return;
    int c = idx % EMB;
    int t = (idx / EMB) & (SEQ - 1);
    int b = idx / (EMB * SEQ);
    int w = t >> 3, h = t & 7;
    g_x[idx] = img[(((size_t)b * EMB + c) * 8 + h) * 64 + w];
}

// ---------------------------------------------------------------
// LayerNorm over E=192. One warp per row, 6 elems per lane.
// ---------------------------------------------------------------
__global__ __launch_bounds__(256) void k_ln192(
    const float* __restrict__ in, float* __restrict__ out,
    const float* __restrict__ gam, const float* __restrict__ bet) {
    int row  = blockIdx.x * 8 + (threadIdx.x >> 5);
    int lane = threadIdx.x & 31;
    const float* p = in + (size_t)row * EMB;
    float v[6];
    float s = 0.f;
#pragma unroll
    for (int i = 0; i < 6; i++) { v[i] = p[lane + 32 * i]; s += v[i]; }
#pragma unroll
    for (int o = 16; o; o >>= 1) s += __shfl_xor_sync(0xffffffffu, s, o);
    float mu = s * (1.f / 192.f);
    float q = 0.f;
#pragma unroll
    for (int i = 0; i < 6; i++) { float d = v[i] - mu; q += d * d; }
#pragma unroll
    for (int o = 16; o; o >>= 1) q += __shfl_xor_sync(0xffffffffu, q, o);
    float rstd = rsqrtf(q * (1.f / 192.f) + 1e-5f);
    float* op = out + (size_t)row * EMB;
#pragma unroll
    for (int i = 0; i < 6; i++) {
        int c = lane + 32 * i;
        op[c] = (v[i] - mu) * rstd * gam[c] + bet[c];
    }
}

// ---------------------------------------------------------------
// GEMM: C[M,N] = A[M,K] @ W[N,K]^T + bias[N] (+ReLU) (+residual R[M,N])
// BM=BN=64, BK=16; 256 threads; 4x4 per thread; float4 smem compute reads.
// All dims are multiples of the tile sizes (no bounds checks).
// ---------------------------------------------------------------
template <int RELU, int RES>
__global__ __launch_bounds__(256) void k_gemm(
    const float* __restrict__ A, const float* __restrict__ W,
    const float* __restrict__ bias, const float* __restrict__ R,
    float* __restrict__ C, int M, int N, int K) {
    __shared__ float As[16][64];
    __shared__ float Ws[16][64];
    int bn = blockIdx.x * 64;
    int bm = blockIdx.y * 64;
    int tid = threadIdx.x;
    int tx = tid & 15, ty = tid >> 4;
    int lrow = tid >> 2;
    int lcol = (tid & 3) << 2;
    float acc[4][4];
#pragma unroll
    for (int i = 0; i < 4; i++)
#pragma unroll
        for (int j = 0; j < 4; j++) acc[i][j] = 0.f;

    const float* ap = A + (size_t)(bm + lrow) * K + lcol;
    const float* wp = W + (size_t)(bn + lrow) * K + lcol;

    for (int k0 = 0; k0 < K; k0 += 16) {
        float4 av = *(const float4*)(ap + k0);
        float4 wv = *(const float4*)(wp + k0);
        __syncthreads();
        As[lcol + 0][lrow] = av.x; As[lcol + 1][lrow] = av.y;
        As[lcol + 2][lrow] = av.z; As[lcol + 3][lrow] = av.w;
        Ws[lcol + 0][lrow] = wv.x; Ws[lcol + 1][lrow] = wv.y;
        Ws[lcol + 2][lrow] = wv.z; Ws[lcol + 3][lrow] = wv.w;
        __syncthreads();
#pragma unroll
        for (int kk = 0; kk < 16; kk++) {
            float4 a4 = *(const float4*)&As[kk][ty * 4];
            float4 w4 = *(const float4*)&Ws[kk][tx * 4];
            float ar[4] = {a4.x, a4.y, a4.z, a4.w};
            float wr[4] = {w4.x, w4.y, w4.z, w4.w};
#pragma unroll
            for (int i = 0; i < 4; i++)
#pragma unroll
                for (int j = 0; j < 4; j++) acc[i][j] += ar[i] * wr[j];
        }
    }

    float4 bv = *(const float4*)(bias + bn + tx * 4);
#pragma unroll
    for (int i = 0; i < 4; i++) {
        int m = bm + ty * 4 + i;
        float4 v;
        v.x = acc[i][0] + bv.x; v.y = acc[i][1] + bv.y;
        v.z = acc[i][2] + bv.z; v.w = acc[i][3] + bv.w;
        if (RELU) {
            v.x = fmaxf(v.x, 0.f); v.y = fmaxf(v.y, 0.f);
            v.z = fmaxf(v.z, 0.f); v.w = fmaxf(v.w, 0.f);
        }
        if (RES) {
            float4 r = *(const float4*)(R + (size_t)m * N + bn + tx * 4);
            v.x += r.x; v.y += r.y; v.z += r.z; v.w += r.w;
        }
        *(float4*)(C + (size_t)m * N + bn + tx * 4) = v;
    }
}

// ---------------------------------------------------------------
// Attention: qkv [B, S, 576] (q|k|v blocks of 192). 1 query per thread,
// 128 queries per block, online softmax over 8 key tiles of 64.
// Mask (local blocks): masked iff |q/64 - k/64| <= 3 && |q%64 - k%64| <= 5
// (the reference masks *inside* the window: anti-local attention).
// ---------------------------------------------------------------
__global__ __launch_bounds__(128) void k_attn(
    const float* __restrict__ qkv, float* __restrict__ out, int local) {
    int qt = blockIdx.x, hh = blockIdx.y, b = blockIdx.z;
    int tid = threadIdx.x;
    __shared__ float4 Ks[64][8];
    __shared__ float4 Vs[64][8];
    const float* base = qkv + (size_t)b * SEQ * 576;
    int qg = qt * 128 + tid;
    float qr[32];
    const float* qp = base + (size_t)qg * 576 + hh * HD;
#pragma unroll
    for (int i = 0; i < 32; i++) qr[i] = qp[i] * 0.17677669529663687f; // 1/sqrt(32)

    float mrun = -1e30f, lrun = 0.f;
    float acc[32];
#pragma unroll
    for (int i = 0; i < 32; i++) acc[i] = 0.f;

    for (int kt = 0; kt < 8; kt++) {
        __syncthreads();
        {
            int r = tid >> 1;
            int c = (tid & 1) * 4;   // float4 index
            const float4* kp = (const float4*)(base + (size_t)(kt * 64 + r) * 576 + EMB     + hh * HD) + c;
            const float4* vp = (const float4*)(base + (size_t)(kt * 64 + r) * 576 + 2 * EMB + hh * HD) + c;
#pragma unroll
            for (int q = 0; q < 4; q++) { Ks[r][c + q] = kp[q]; Vs[r][c + q] = vp[q]; }
        }
        __syncthreads();

        float s[64];
#pragma unroll
        for (int j = 0; j < 64; j++) {
            float d = 0.f;
#pragma unroll
            for (int i4 = 0; i4 < 8; i4++) {
                float4 kv = Ks[j][i4];
                d += qr[i4 * 4 + 0] * kv.x + qr[i4 * 4 + 1] * kv.y
                   + qr[i4 * 4 + 2] * kv.z + qr[i4 * 4 + 3] * kv.w;
            }
            s[j] = d;
        }
        if (local) {
            int dr = (qg >> 6) - kt;
            if (dr <= 3 && dr >= -3) {
                int qw = qg & 63;
#pragma unroll
                for (int j = 0; j < 64; j++) {
                    int dw = qw - j;
                    if (dw <= 5 && dw >= -5) s[j] = -1e30f;
                }
            }
        }
        float tm = s[0];
#pragma unroll
        for (int j = 1; j < 64; j++) tm = fmaxf(tm, s[j]);
        float mn = fmaxf(mrun, tm);
        float sc = __expf(mrun - mn);
        lrun *= sc;
#pragma unroll
        for (int i = 0; i < 32; i++) acc[i] *= sc;
#pragma unroll
        for (int j = 0; j < 64; j++) {
            float p = __expf(s[j] - mn);
            lrun += p;
#pragma unroll
            for (int i4 = 0; i4 < 8; i4++) {
                float4 vv = Vs[j][i4];
                acc[i4 * 4 + 0] += p * vv.x;
                acc[i4 * 4 + 1] += p * vv.y;
                acc[i4 * 4 + 2] += p * vv.z;
                acc[i4 * 4 + 3] += p * vv.w;
            }
        }
        mrun = mn;
    }
    float inv = 1.f / lrun;
    float* op = out + (size_t)(b * SEQ + qg) * EMB + hh * HD;
#pragma unroll
    for (int i = 0; i < 32; i++) op[i] = acc[i] * inv;
}

// ---------------------------------------------------------------
// Merge: conv (3,1) stride (2,1) pad (1,0) over [B, C=192, 8, 64] -> [B, 256, 4, 64]
// then channel LayerNorm over the 256 output channels. Fused.
// One block per (b, ho, 4 w-positions), 256 threads = 256 output channels.
// Reads x directly in token layout: x_img[b, ci, hh, w] = g_x[b, w*8+hh, ci]
// ---------------------------------------------------------------
__global__ __launch_bounds__(256) void k_merge(
    const float* __restrict__ cw, const float* __restrict__ cb,
    const float* __restrict__ mg, const float* __restrict__ mb,
    float* __restrict__ out) {
    int blk = blockIdx.x;           // 64 * 4 * 16 = 4096
    int wg = blk & 15;
    int ho = (blk >> 4) & 3;
    int b  = blk >> 6;
    int co = threadIdx.x;
    __shared__ float xs[4][3][EMB];
    __shared__ float red[256];

    for (int idx = co; idx < 4 * 3 * EMB; idx += 256) {
        int g   = idx / (3 * EMB);
        int rem = idx - g * (3 * EMB);
        int kh  = rem / EMB;
        int ci  = rem - kh * EMB;
        int hh  = 2 * ho - 1 + kh;
        int w   = wg * 4 + g;
        float v = 0.f;
        if (hh >= 0 && hh < 8)
            v = g_x[((size_t)b * SEQ + (w * 8 + hh)) * EMB + ci];
        xs[g][kh][ci] = v;
    }
    __syncthreads();

    float bias = cb[co];
    float acc[4] = {bias, bias, bias, bias};
    const float* wp = cw + (size_t)co * (EMB * 3);   // [ci][kh], kh contiguous
    for (int ci = 0; ci < EMB; ci++) {
        float w0 = wp[ci * 3 + 0], w1 = wp[ci * 3 + 1], w2 = wp[ci * 3 + 2];
#pragma unroll
        for (int g = 0; g < 4; g++)
            acc[g] += xs[g][0][ci] * w0 + xs[g][1][ci] * w1 + xs[g][2][ci] * w2;
    }

#pragma unroll
    for (int g = 0; g < 4; g++) {
        __syncthreads();
        red[co] = acc[g];
        __syncthreads();
        for (int s = 128; s > 0; s >>= 1) {
            if (co < s) red[co] += red[co + s];
            __syncthreads();
        }
        float mu = red[0] * (1.f / 256.f);
        __syncthreads();
        float d = acc[g] - mu;
        red[co] = d * d;
        __syncthreads();
        for (int s = 128; s > 0; s >>= 1) {
            if (co < s) red[co] += red[co + s];
            __syncthreads();
        }
        float rstd = rsqrtf(red[0] * (1.f / 256.f) + 1e-5f);
        int w = wg * 4 + g;
        out[(((size_t)b * 256 + co) * 4 + ho) * 64 + w] = d * rstd * mg[co] + mb[co];
    }
}

// ---------------------------------------------------------------
extern "C" void kernel_launch(void* const* d_in, const int* in_sizes, int n_in,
                              void* d_out, int out_size) {
    const float* image = (const float*)d_in[0];
    const float* in_w  = (const float*)d_in[1];
    const float* in_b  = (const float*)d_in[2];
    const float* out_w = (const float*)d_in[3];
    const float* out_b = (const float*)d_in[4];
    const float* ln1_g = (const float*)d_in[5];
    const float* ln1_b = (const float*)d_in[6];
    const float* ln2_g = (const float*)d_in[7];
    const float* ln2_b = (const float*)d_in[8];
    const float* w1    = (const float*)d_in[9];
    const float* b1    = (const float*)d_in[10];
    const float* w2    = (const float*)d_in[11];
    const float* b2    = (const float*)d_in[12];
    const float* convw = (const float*)d_in[13];
    const float* convb = (const float*)d_in[14];
    const float* mlng  = (const float*)d_in[15];
    const float* mlnb  = (const float*)d_in[16];

    float *px, *pxn, *pbig, *pattn;
    cudaGetSymbolAddress((void**)&px,    g_x);
    cudaGetSymbolAddress((void**)&pxn,   g_xn);
    cudaGetSymbolAddress((void**)&pbig,  g_big);
    cudaGetSymbolAddress((void**)&pattn, g_attn);

    k_tin<<<(BATCH * SEQ * EMB + 255) / 256, 256>>>(image);

    for (int l = 0; l < 6; l++) {
        int local = (l >= 2);  // LOCAL = (F, F, T, T, T, T)
        // xn = LN1(x)
        k_ln192<<<MROWS / 8, 256>>>(px, pxn, ln1_g + l * EMB, ln1_b + l * EMB);
        // qkv = xn @ Wi^T + bi   [32768, 576]
        k_gemm<0, 0><<<dim3(9, MROWS / 64), 256>>>(
            pxn, in_w + (size_t)l * 576 * EMB, in_b + l * 576,
            nullptr, pbig, MROWS, 576, EMB);
        // attn = softmax(qk^T/sqrt(hd) [mask]) @ v  -> [32768, 192]
        k_attn<<<dim3(4, NHEAD, BATCH), 128>>>(pbig, pattn, local);
        // x = attn @ Wo^T + bo + xn   (residual uses post-LN xn!)
        k_gemm<0, 1><<<dim3(3, MROWS / 64), 256>>>(
            pattn, out_w + (size_t)l * EMB * EMB, out_b + l * EMB,
            pxn, px, MROWS, EMB, EMB);
        // xn = LN2(x)
        k_ln192<<<MROWS / 8, 256>>>(px, pxn, ln2_g + l * EMB, ln2_b + l * EMB);
        // h = relu(xn @ w1^T + b1)   [32768, 768]
        k_gemm<1, 0><<<dim3(12, MROWS / 64), 256>>>(
            pxn, w1 + (size_t)l * 768 * EMB, b1 + l * 768,
            nullptr, pbig, MROWS, 768, EMB);
        // x = h @ w2^T + b2 + xn     (residual uses post-LN xn!)
        k_gemm<0, 1><<<dim3(3, MROWS / 64), 256>>>(
            pbig, w2 + (size_t)l * EMB * 768, b2 + l * EMB,
            pxn, px, MROWS, EMB, 768);
    }

    k_merge<<<4096, 256>>>(convw, convb, mlng, mlnb, (float*)d_out);
}

// round 3
// speedup vs baseline: 1.5111x; 1.5111x over previous
#include <cuda_runtime.h>
#include <math.h>
#include <stdint.h>

#define BATCH 64
#define SEQ   512
#define EMB   192
#define NHEAD 6
#define HD    32
#define MROWS (BATCH * SEQ)   // 32768

// -------- scratch (device globals; no runtime allocation) --------
__device__ float g_x   [BATCH * SEQ * EMB];   // residual stream
__device__ float g_xn  [BATCH * SEQ * EMB];   // LN output
__device__ float g_big [BATCH * SEQ * 768];   // qkv (576 used) / mlp hidden (768)
__device__ float g_attn[BATCH * SEQ * EMB];   // attention head-merged output

// ---------------------------------------------------------------
// input transpose: image [B, C, H, W] -> x [B, S=W*H, C], token t = w*8 + h
// ---------------------------------------------------------------
__global__ void k_tin(const float* __restrict__ img) {
    int idx = blockIdx.x * 256 + threadIdx.x;
    if (idx >= BATCH * SEQ * EMB) return;
    int c = idx % EMB;
    int t = (idx / EMB) & (SEQ - 1);
    int b = idx / (EMB * SEQ);
    int w = t >> 3, h = t & 7;
    g_x[idx] = img[(((size_t)b * EMB + c) * 8 + h) * 64 + w];
}

// ---------------------------------------------------------------
// LayerNorm over E=192. One warp per row, 6 elems per lane.
// ---------------------------------------------------------------
__global__ __launch_bounds__(256) void k_ln192(
    const float* __restrict__ in, float* __restrict__ out,
    const float* __restrict__ gam, const float* __restrict__ bet) {
    int row  = blockIdx.x * 8 + (threadIdx.x >> 5);
    int lane = threadIdx.x & 31;
    const float* p = in + (size_t)row * EMB;
    float v[6];
    float s = 0.f;
#pragma unroll
    for (int i = 0; i < 6; i++) { v[i] = p[lane + 32 * i]; s += v[i]; }
#pragma unroll
    for (int o = 16; o; o >>= 1) s += __shfl_xor_sync(0xffffffffu, s, o);
    float mu = s * (1.f / 192.f);
    float q = 0.f;
#pragma unroll
    for (int i = 0; i < 6; i++) { float d = v[i] - mu; q += d * d; }
#pragma unroll
    for (int o = 16; o; o >>= 1) q += __shfl_xor_sync(0xffffffffu, q, o);
    float rstd = rsqrtf(q * (1.f / 192.f) + 1e-5f);
    float* op = out + (size_t)row * EMB;
#pragma unroll
    for (int i = 0; i < 6; i++) {
        int c = lane + 32 * i;
        op[c] = (v[i] - mu) * rstd * gam[c] + bet[c];
    }
}

// ---------------------------------------------------------------
// tf32 tensor-core GEMM (legacy mma.sync path — sm_103 non-'a' target):
// C[M,Ntot] = A[M,K] @ W[Ntot,K]^T + bias (+ReLU) (+residual)
// BM=128, BN=64, BK=32; 256 threads = 8 warps (4x2); warp tile 32x32.
// Double-buffered cp.async. Smem pitch 36 floats (conflict-free frags).
// ---------------------------------------------------------------
#define PITCH 36
#define STAGE_F (128 * PITCH + 64 * PITCH)   // 6912 floats = 27648 B
#define GSMEM_BYTES (2 * STAGE_F * 4)        // 55296 B

__device__ __forceinline__ uint32_t to_tf32(float v) {
    uint32_t r;
    asm("cvt.rna.tf32.f32 %0, %1;" : "=r"(r) : "f"(v));
    return r;
}
__device__ __forceinline__ void cp16g(float* dst, const float* src) {
    uint32_t d;
    asm("{ .reg .u64 t; cvta.to.shared.u64 t, %1; cvt.u32.u64 %0, t; }"
        : "=r"(d) : "l"(dst));
    asm volatile("cp.async.cg.shared.global [%0], [%1], 16;" :: "r"(d), "l"(src));
}

template <int RELU, int RES>
__global__ __launch_bounds__(256, 2) void k_gemm_tc(
    const float* __restrict__ A, const float* __restrict__ W,
    const float* __restrict__ bias, const float* __restrict__ R,
    float* __restrict__ C, int Ntot, int K) {
    extern __shared__ float sh[];

    const int bm = blockIdx.y * 128;
    const int bn = blockIdx.x * 64;
    const int tid = threadIdx.x;
    const int wid = tid >> 5;
    const int lane = tid & 31;
    const int wm = wid >> 1;           // 0..3
    const int wn = wid & 1;            // 0..1
    const int g  = lane >> 2;          // group id 0..7
    const int tg = lane & 3;           // thread in group

    const int KT = K >> 5;

    auto load_stage = [&](int kt, int s) {
        float* as = sh + s * STAGE_F;
        float* bs = as + 128 * PITCH;
        const float* Ab = A + (size_t)bm * K + kt * 32;
        const float* Wb = W + (size_t)bn * K + kt * 32;
#pragma unroll
        for (int i = 0; i < 4; i++) {
            int id = tid + i * 256;            // 0..1023 : A chunks
            int r = id >> 3, c = id & 7;
            cp16g(as + r * PITCH + c * 4, Ab + (size_t)r * K + c * 4);
        }
#pragma unroll
        for (int i = 0; i < 2; i++) {
            int id = tid + i * 256;            // 0..511 : B chunks
            int r = id >> 3, c = id & 7;
            cp16g(bs + r * PITCH + c * 4, Wb + (size_t)r * K + c * 4);
        }
        asm volatile("cp.async.commit_group;" ::: "memory");
    };

    float acc[2][4][4];
#pragma unroll
    for (int mm = 0; mm < 2; mm++)
#pragma unroll
        for (int nn = 0; nn < 4; nn++)
#pragma unroll
            for (int r = 0; r < 4; r++) acc[mm][nn][r] = 0.f;

    load_stage(0, 0);
    for (int kt = 0; kt < KT; kt++) {
        int s = kt & 1;
        if (kt + 1 < KT) {
            load_stage(kt + 1, s ^ 1);
            asm volatile("cp.async.wait_group 1;" ::: "memory");
        } else {
            asm volatile("cp.async.wait_group 0;" ::: "memory");
        }
        __syncthreads();

        const float* as = sh + s * STAGE_F;
        const float* bs = as + 128 * PITCH;
#pragma unroll
        for (int ks = 0; ks < 4; ks++) {
            int k0 = ks * 8;
            uint32_t a[2][4], b[4][2];
#pragma unroll
            for (int mm = 0; mm < 2; mm++) {
                int r0 = wm * 32 + mm * 16 + g;
                a[mm][0] = to_tf32(as[r0 * PITCH + k0 + tg]);
                a[mm][1] = to_tf32(as[(r0 + 8) * PITCH + k0 + tg]);
                a[mm][2] = to_tf32(as[r0 * PITCH + k0 + tg + 4]);
                a[mm][3] = to_tf32(as[(r0 + 8) * PITCH + k0 + tg + 4]);
            }
#pragma unroll
            for (int nn = 0; nn < 4; nn++) {
                int n0 = wn * 32 + nn * 8 + g;
                b[nn][0] = to_tf32(bs[n0 * PITCH + k0 + tg]);
                b[nn][1] = to_tf32(bs[n0 * PITCH + k0 + tg + 4]);
            }
#pragma unroll
            for (int mm = 0; mm < 2; mm++)
#pragma unroll
                for (int nn = 0; nn < 4; nn++) {
                    float* c = acc[mm][nn];
                    asm volatile(
                        "mma.sync.aligned.m16n8k8.row.col.f32.tf32.tf32.f32 "
                        "{%0,%1,%2,%3}, {%4,%5,%6,%7}, {%8,%9}, {%0,%1,%2,%3};"
                        : "+f"(c[0]), "+f"(c[1]), "+f"(c[2]), "+f"(c[3])
                        : "r"(a[mm][0]), "r"(a[mm][1]), "r"(a[mm][2]), "r"(a[mm][3]),
                          "r"(b[nn][0]), "r"(b[nn][1]));
                }
        }
        __syncthreads();
    }

    // epilogue: c0/c1 at (row, 2tg..2tg+1), c2/c3 at (row+8, ...)
#pragma unroll
    for (int mm = 0; mm < 2; mm++) {
#pragma unroll
        for (int half = 0; half < 2; half++) {
            int m = bm + wm * 32 + mm * 16 + g + half * 8;
            float* crow = C + (size_t)m * Ntot + bn;
            const float* rrow = RES ? (R + (size_t)m * Ntot + bn) : (const float*)0;
#pragma unroll
            for (int nn = 0; nn < 4; nn++) {
                int n = wn * 32 + nn * 8 + 2 * tg;
                float2 v;
                v.x = acc[mm][nn][half * 2 + 0] + bias[bn + n];
                v.y = acc[mm][nn][half * 2 + 1] + bias[bn + n + 1];
                if (RELU) { v.x = fmaxf(v.x, 0.f); v.y = fmaxf(v.y, 0.f); }
                if (RES) {
                    float2 r2 = *(const float2*)(rrow + n);
                    v.x += r2.x; v.y += r2.y;
                }
                *(float2*)(crow + n) = v;
            }
        }
    }
}

// ---------------------------------------------------------------
// Attention: qkv [B, S, 576] (q|k|v blocks of 192). 1 query per thread.
// Mask (local blocks): masked iff |q/64 - k/64| <= 3 && |q%64 - k%64| <= 5
// ---------------------------------------------------------------
__global__ __launch_bounds__(128) void k_attn(
    const float* __restrict__ qkv, float* __restrict__ out, int local) {
    int qt = blockIdx.x, hh = blockIdx.y, b = blockIdx.z;
    int tid = threadIdx.x;
    __shared__ float4 Ks[64][8];
    __shared__ float4 Vs[64][8];
    const float* base = qkv + (size_t)b * SEQ * 576;
    int qg = qt * 128 + tid;
    float qr[32];
    const float* qp = base + (size_t)qg * 576 + hh * HD;
#pragma unroll
    for (int i = 0; i < 32; i++) qr[i] = qp[i] * 0.17677669529663687f;

    float mrun = -1e30f, lrun = 0.f;
    float acc[32];
#pragma unroll
    for (int i = 0; i < 32; i++) acc[i] = 0.f;

    for (int kt = 0; kt < 8; kt++) {
        __syncthreads();
        {
            int r = tid >> 1;
            int c = (tid & 1) * 4;
            const float4* kp = (const float4*)(base + (size_t)(kt * 64 + r) * 576 + EMB     + hh * HD) + c;
            const float4* vp = (const float4*)(base + (size_t)(kt * 64 + r) * 576 + 2 * EMB + hh * HD) + c;
#pragma unroll
            for (int q = 0; q < 4; q++) { Ks[r][c + q] = kp[q]; Vs[r][c + q] = vp[q]; }
        }
        __syncthreads();

        float s[64];
#pragma unroll
        for (int j = 0; j < 64; j++) {
            float d = 0.f;
#pragma unroll
            for (int i4 = 0; i4 < 8; i4++) {
                float4 kv = Ks[j][i4];
                d += qr[i4 * 4 + 0] * kv.x + qr[i4 * 4 + 1] * kv.y
                   + qr[i4 * 4 + 2] * kv.z + qr[i4 * 4 + 3] * kv.w;
            }
            s[j] = d;
        }
        if (local) {
            int dr = (qg >> 6) - kt;
            if (dr <= 3 && dr >= -3) {
                int qw = qg & 63;
#pragma unroll
                for (int j = 0; j < 64; j++) {
                    int dw = qw - j;
                    if (dw <= 5 && dw >= -5) s[j] = -1e30f;
                }
            }
        }
        float tm = s[0];
#pragma unroll
        for (int j = 1; j < 64; j++) tm = fmaxf(tm, s[j]);
        float mn = fmaxf(mrun, tm);
        float sc = __expf(mrun - mn);
        lrun *= sc;
#pragma unroll
        for (int i = 0; i < 32; i++) acc[i] *= sc;
#pragma unroll
        for (int j = 0; j < 64; j++) {
            float p = __expf(s[j] - mn);
            lrun += p;
#pragma unroll
            for (int i4 = 0; i4 < 8; i4++) {
                float4 vv = Vs[j][i4];
                acc[i4 * 4 + 0] += p * vv.x;
                acc[i4 * 4 + 1] += p * vv.y;
                acc[i4 * 4 + 2] += p * vv.z;
                acc[i4 * 4 + 3] += p * vv.w;
            }
        }
        mrun = mn;
    }
    float inv = 1.f / lrun;
    float* op = out + (size_t)(b * SEQ + qg) * EMB + hh * HD;
#pragma unroll
    for (int i = 0; i < 32; i++) op[i] = acc[i] * inv;
}

// ---------------------------------------------------------------
// Merge: conv (3,1) stride (2,1) pad (1,0) + channel LN, fused.
// ---------------------------------------------------------------
__global__ __launch_bounds__(256) void k_merge(
    const float* __restrict__ cw, const float* __restrict__ cb,
    const float* __restrict__ mg, const float* __restrict__ mb,
    float* __restrict__ out) {
    int blk = blockIdx.x;
    int wg = blk & 15;
    int ho = (blk >> 4) & 3;
    int b  = blk >> 6;
    int co = threadIdx.x;
    __shared__ float xs[4][3][EMB];
    __shared__ float red[256];

    for (int idx = co; idx < 4 * 3 * EMB; idx += 256) {
        int g   = idx / (3 * EMB);
        int rem = idx - g * (3 * EMB);
        int kh  = rem / EMB;
        int ci  = rem - kh * EMB;
        int hh  = 2 * ho - 1 + kh;
        int w   = wg * 4 + g;
        float v = 0.f;
        if (hh >= 0 && hh < 8)
            v = g_x[((size_t)b * SEQ + (w * 8 + hh)) * EMB + ci];
        xs[g][kh][ci] = v;
    }
    __syncthreads();

    float bias = cb[co];
    float acc[4] = {bias, bias, bias, bias};
    const float* wp = cw + (size_t)co * (EMB * 3);
    for (int ci = 0; ci < EMB; ci++) {
        float w0 = wp[ci * 3 + 0], w1 = wp[ci * 3 + 1], w2 = wp[ci * 3 + 2];
#pragma unroll
        for (int g = 0; g < 4; g++)
            acc[g] += xs[g][0][ci] * w0 + xs[g][1][ci] * w1 + xs[g][2][ci] * w2;
    }

#pragma unroll
    for (int g = 0; g < 4; g++) {
        __syncthreads();
        red[co] = acc[g];
        __syncthreads();
        for (int s = 128; s > 0; s >>= 1) {
            if (co < s) red[co] += red[co + s];
            __syncthreads();
        }
        float mu = red[0] * (1.f / 256.f);
        __syncthreads();
        float d = acc[g] - mu;
        red[co] = d * d;
        __syncthreads();
        for (int s = 128; s > 0; s >>= 1) {
            if (co < s) red[co] += red[co + s];
            __syncthreads();
        }
        float rstd = rsqrtf(red[0] * (1.f / 256.f) + 1e-5f);
        int w = wg * 4 + g;
        out[(((size_t)b * 256 + co) * 4 + ho) * 64 + w] = d * rstd * mg[co] + mb[co];
    }
}

// ---------------------------------------------------------------
extern "C" void kernel_launch(void* const* d_in, const int* in_sizes, int n_in,
                              void* d_out, int out_size) {
    const float* image = (const float*)d_in[0];
    const float* in_w  = (const float*)d_in[1];
    const float* in_b  = (const float*)d_in[2];
    const float* out_w = (const float*)d_in[3];
    const float* out_b = (const float*)d_in[4];
    const float* ln1_g = (const float*)d_in[5];
    const float* ln1_b = (const float*)d_in[6];
    const float* ln2_g = (const float*)d_in[7];
    const float* ln2_b = (const float*)d_in[8];
    const float* w1    = (const float*)d_in[9];
    const float* b1    = (const float*)d_in[10];
    const float* w2    = (const float*)d_in[11];
    const float* b2    = (const float*)d_in[12];
    const float* convw = (const float*)d_in[13];
    const float* convb = (const float*)d_in[14];
    const float* mlng  = (const float*)d_in[15];
    const float* mlnb  = (const float*)d_in[16];

    float *px, *pxn, *pbig, *pattn;
    cudaGetSymbolAddress((void**)&px,    g_x);
    cudaGetSymbolAddress((void**)&pxn,   g_xn);
    cudaGetSymbolAddress((void**)&pbig,  g_big);
    cudaGetSymbolAddress((void**)&pattn, g_attn);

    cudaFuncSetAttribute(k_gemm_tc<0, 0>, cudaFuncAttributeMaxDynamicSharedMemorySize, GSMEM_BYTES);
    cudaFuncSetAttribute(k_gemm_tc<0, 1>, cudaFuncAttributeMaxDynamicSharedMemorySize, GSMEM_BYTES);
    cudaFuncSetAttribute(k_gemm_tc<1, 0>, cudaFuncAttributeMaxDynamicSharedMemorySize, GSMEM_BYTES);

    k_tin<<<(BATCH * SEQ * EMB + 255) / 256, 256>>>(image);

    for (int l = 0; l < 6; l++) {
        int local = (l >= 2);  // LOCAL = (F, F, T, T, T, T)
        // xn = LN1(x)
        k_ln192<<<MROWS / 8, 256>>>(px, pxn, ln1_g + l * EMB, ln1_b + l * EMB);
        // qkv = xn @ Wi^T + bi   [32768, 576]
        k_gemm_tc<0, 0><<<dim3(9, MROWS / 128), 256, GSMEM_BYTES>>>(
            pxn, in_w + (size_t)l * 576 * EMB, in_b + l * 576,
            nullptr, pbig, 576, EMB);
        // attn = softmax(qk^T/sqrt(hd) [mask]) @ v
        k_attn<<<dim3(4, NHEAD, BATCH), 128>>>(pbig, pattn, local);
        // x = attn @ Wo^T + bo + xn   (residual uses post-LN xn!)
        k_gemm_tc<0, 1><<<dim3(3, MROWS / 128), 256, GSMEM_BYTES>>>(
            pattn, out_w + (size_t)l * EMB * EMB, out_b + l * EMB,
            pxn, px, EMB, EMB);
        // xn = LN2(x)
        k_ln192<<<MROWS / 8, 256>>>(px, pxn, ln2_g + l * EMB, ln2_b + l * EMB);
        // h = relu(xn @ w1^T + b1)   [32768, 768]
        k_gemm_tc<1, 0><<<dim3(12, MROWS / 128), 256, GSMEM_BYTES>>>(
            pxn, w1 + (size_t)l * 768 * EMB, b1 + l * 768,
            nullptr, pbig, 768, EMB);
        // x = h @ w2^T + b2 + xn     (residual uses post-LN xn!)
        k_gemm_tc<0, 1><<<dim3(3, MROWS / 128), 256, GSMEM_BYTES>>>(
            pbig, w2 + (size_t)l * EMB * 768, b2 + l * EMB,
            pxn, px, EMB, 768);
    }

    k_merge<<<4096, 256>>>(convw, convb, mlng, mlnb, (float*)d_out);
}

// round 4
// speedup vs baseline: 2.2947x; 1.5185x over previous
#include <cuda_runtime.h>
#include <math.h>
#include <stdint.h>

#define BATCH 64
#define SEQ   512
#define EMB   192
#define NHEAD 6
#define HD    32
#define MROWS (BATCH * SEQ)   // 32768

// -------- scratch (device globals; no runtime allocation) --------
__device__ float g_x   [BATCH * SEQ * EMB];   // residual stream
__device__ float g_xn  [BATCH * SEQ * EMB];   // LN output
__device__ float g_big [BATCH * SEQ * 768];   // qkv (576 used) / mlp hidden (768)
__device__ float g_attn[BATCH * SEQ * EMB];   // attention head-merged output

__device__ __forceinline__ uint32_t to_tf32(float v) {
    uint32_t r;
    asm("cvt.rna.tf32.f32 %0, %1;" : "=r"(r) : "f"(v));
    return r;
}
__device__ __forceinline__ float tf32f(float v) {
    return __uint_as_float(to_tf32(v));
}
__device__ __forceinline__ void mma_tf32(float* c, const uint32_t* a,
                                         uint32_t b0, uint32_t b1) {
    asm volatile(
        "mma.sync.aligned.m16n8k8.row.col.f32.tf32.tf32.f32 "
        "{%0,%1,%2,%3}, {%4,%5,%6,%7}, {%8,%9}, {%0,%1,%2,%3};"
        : "+f"(c[0]), "+f"(c[1]), "+f"(c[2]), "+f"(c[3])
        : "r"(a[0]), "r"(a[1]), "r"(a[2]), "r"(a[3]), "r"(b0), "r"(b1));
}
__device__ __forceinline__ void cp16g(float* dst, const float* src) {
    uint32_t d;
    asm("{ .reg .u64 t; cvta.to.shared.u64 t, %1; cvt.u32.u64 %0, t; }"
        : "=r"(d) : "l"(dst));
    asm volatile("cp.async.cg.shared.global [%0], [%1], 16;" :: "r"(d), "l"(src));
}

// ---------------------------------------------------------------
// input transpose: image [B, C, H, W] -> x [B, S=W*H, C], token t = w*8 + h
// ---------------------------------------------------------------
__global__ void k_tin(const float* __restrict__ img) {
    int idx = blockIdx.x * 256 + threadIdx.x;
    if (idx >= BATCH * SEQ * EMB) return;
    int c = idx % EMB;
    int t = (idx / EMB) & (SEQ - 1);
    int b = idx / (EMB * SEQ);
    int w = t >> 3, h = t & 7;
    g_x[idx] = img[(((size_t)b * EMB + c) * 8 + h) * 64 + w];
}

// ---------------------------------------------------------------
// LayerNorm over E=192. One warp per row, 6 elems per lane.
// ---------------------------------------------------------------
__global__ __launch_bounds__(256) void k_ln192(
    const float* __restrict__ in, float* __restrict__ out,
    const float* __restrict__ gam, const float* __restrict__ bet) {
    int row  = blockIdx.x * 8 + (threadIdx.x >> 5);
    int lane = threadIdx.x & 31;
    const float* p = in + (size_t)row * EMB;
    float v[6];
    float s = 0.f;
#pragma unroll
    for (int i = 0; i < 6; i++) { v[i] = p[lane + 32 * i]; s += v[i]; }
#pragma unroll
    for (int o = 16; o; o >>= 1) s += __shfl_xor_sync(0xffffffffu, s, o);
    float mu = s * (1.f / 192.f);
    float q = 0.f;
#pragma unroll
    for (int i = 0; i < 6; i++) { float d = v[i] - mu; q += d * d; }
#pragma unroll
    for (int o = 16; o; o >>= 1) q += __shfl_xor_sync(0xffffffffu, q, o);
    float rstd = rsqrtf(q * (1.f / 192.f) + 1e-5f);
    float* op = out + (size_t)row * EMB;
#pragma unroll
    for (int i = 0; i < 6; i++) {
        int c = lane + 32 * i;
        op[c] = (v[i] - mu) * rstd * gam[c] + bet[c];
    }
}

// ---------------------------------------------------------------
// tf32 tensor-core GEMM (legacy mma.sync path):
// C[M,Ntot] = A[M,K] @ W[Ntot,K]^T + bias (+ReLU) (+residual)
// BM=128, BN=64, BK=32; 256 threads = 8 warps (4x2); warp tile 32x32.
// ---------------------------------------------------------------
#define PITCH 36
#define STAGE_F (128 * PITCH + 64 * PITCH)   // 6912 floats
#define GSMEM_BYTES (2 * STAGE_F * 4)        // 55296 B

template <int RELU, int RES>
__global__ __launch_bounds__(256, 2) void k_gemm_tc(
    const float* __restrict__ A, const float* __restrict__ W,
    const float* __restrict__ bias, const float* __restrict__ R,
    float* __restrict__ C, int Ntot, int K) {
    extern __shared__ float sh[];

    const int bm = blockIdx.y * 128;
    const int bn = blockIdx.x * 64;
    const int tid = threadIdx.x;
    const int wid = tid >> 5;
    const int lane = tid & 31;
    const int wm = wid >> 1;
    const int wn = wid & 1;
    const int g  = lane >> 2;
    const int tg = lane & 3;

    const int KT = K >> 5;

    auto load_stage = [&](int kt, int s) {
        float* as = sh + s * STAGE_F;
        float* bs = as + 128 * PITCH;
        const float* Ab = A + (size_t)bm * K + kt * 32;
        const float* Wb = W + (size_t)bn * K + kt * 32;
#pragma unroll
        for (int i = 0; i < 4; i++) {
            int id = tid + i * 256;
            int r = id >> 3, c = id & 7;
            cp16g(as + r * PITCH + c * 4, Ab + (size_t)r * K + c * 4);
        }
#pragma unroll
        for (int i = 0; i < 2; i++) {
            int id = tid + i * 256;
            int r = id >> 3, c = id & 7;
            cp16g(bs + r * PITCH + c * 4, Wb + (size_t)r * K + c * 4);
        }
        asm volatile("cp.async.commit_group;" ::: "memory");
    };

    float acc[2][4][4];
#pragma unroll
    for (int mm = 0; mm < 2; mm++)
#pragma unroll
        for (int nn = 0; nn < 4; nn++)
#pragma unroll
            for (int r = 0; r < 4; r++) acc[mm][nn][r] = 0.f;

    load_stage(0, 0);
    for (int kt = 0; kt < KT; kt++) {
        int s = kt & 1;
        if (kt + 1 < KT) {
            load_stage(kt + 1, s ^ 1);
            asm volatile("cp.async.wait_group 1;" ::: "memory");
        } else {
            asm volatile("cp.async.wait_group 0;" ::: "memory");
        }
        __syncthreads();

        const float* as = sh + s * STAGE_F;
        const float* bs = as + 128 * PITCH;
#pragma unroll
        for (int ks = 0; ks < 4; ks++) {
            int k0 = ks * 8;
            uint32_t a[2][4], b[4][2];
#pragma unroll
            for (int mm = 0; mm < 2; mm++) {
                int r0 = wm * 32 + mm * 16 + g;
                a[mm][0] = to_tf32(as[r0 * PITCH + k0 + tg]);
                a[mm][1] = to_tf32(as[(r0 + 8) * PITCH + k0 + tg]);
                a[mm][2] = to_tf32(as[r0 * PITCH + k0 + tg + 4]);
                a[mm][3] = to_tf32(as[(r0 + 8) * PITCH + k0 + tg + 4]);
            }
#pragma unroll
            for (int nn = 0; nn < 4; nn++) {
                int n0 = wn * 32 + nn * 8 + g;
                b[nn][0] = to_tf32(bs[n0 * PITCH + k0 + tg]);
                b[nn][1] = to_tf32(bs[n0 * PITCH + k0 + tg + 4]);
            }
#pragma unroll
            for (int mm = 0; mm < 2; mm++)
#pragma unroll
                for (int nn = 0; nn < 4; nn++)
                    mma_tf32(acc[mm][nn], a[mm], b[nn][0], b[nn][1]);
        }
        __syncthreads();
    }

#pragma unroll
    for (int mm = 0; mm < 2; mm++) {
#pragma unroll
        for (int half = 0; half < 2; half++) {
            int m = bm + wm * 32 + mm * 16 + g + half * 8;
            float* crow = C + (size_t)m * Ntot + bn;
            const float* rrow = RES ? (R + (size_t)m * Ntot + bn) : (const float*)0;
#pragma unroll
            for (int nn = 0; nn < 4; nn++) {
                int n = wn * 32 + nn * 8 + 2 * tg;
                float2 v;
                v.x = acc[mm][nn][half * 2 + 0] + bias[bn + n];
                v.y = acc[mm][nn][half * 2 + 1] + bias[bn + n + 1];
                if (RELU) { v.x = fmaxf(v.x, 0.f); v.y = fmaxf(v.y, 0.f); }
                if (RES) {
                    float2 r2 = *(const float2*)(rrow + n);
                    v.x += r2.x; v.y += r2.y;
                }
                *(float2*)(crow + n) = v;
            }
        }
    }
}

// ---------------------------------------------------------------
// Tensor-core flash attention (tf32 mma.sync).
// Block: (qtile 128, head, batch); 256 thr = 8 warps; warp = 16 q-rows.
// qkv [B,S,576]; mask (local): |q/64 - k/64|<=3 && |q%64 - k%64|<=5 -> -inf
// ---------------------------------------------------------------
#define APITCH 36
#define VPITCH 68
#define PPITCH 68
#define QS_F   (128 * APITCH)         // 4608
#define KS_F   (64 * APITCH)          // 2304 per buffer
#define VT_F   (32 * VPITCH)          // 2176 per buffer
#define PB_F   (16 * PPITCH)          // 1088 per warp
#define ATTN_SMEM_F (QS_F + 2 * KS_F + 2 * VT_F + 8 * PB_F)
#define ATTN_SMEM_B (ATTN_SMEM_F * 4) // 89088 B

__global__ __launch_bounds__(256, 2) void k_attn_tc(
    const float* __restrict__ qkv, float* __restrict__ out, int local) {
    extern __shared__ float sm[];
    float* Qs = sm;
    float* Ks = Qs + QS_F;
    float* Vt = Ks + 2 * KS_F;
    float* Pb = Vt + 2 * VT_F;

    const int qt = blockIdx.x, hh = blockIdx.y, b = blockIdx.z;
    const int tid = threadIdx.x;
    const int wid = tid >> 5;
    const int lane = tid & 31;
    const int g = lane >> 2, tg = lane & 3;
    const float* base = qkv + (size_t)b * SEQ * 576;
    const float SCALE = 0.17677669529663687f; // 1/sqrt(32)

    // prefetch K/V tile 0 into registers
    float4 kf[2], vf[2];
#pragma unroll
    for (int i = 0; i < 2; i++) {
        int f = tid + i * 256;
        int tok = f >> 3, part = f & 7;
        const float* row = base + (size_t)tok * 576 + hh * HD + part * 4;
        kf[i] = *(const float4*)(row + EMB);
        vf[i] = *(const float4*)(row + 2 * EMB);
    }
    // load + convert Q tile (scaled)
#pragma unroll
    for (int i = 0; i < 4; i++) {
        int f = tid + i * 256;
        int tok = f >> 3, part = f & 7;
        float4 q4 = *(const float4*)(base + (size_t)(qt * 128 + tok) * 576 + hh * HD + part * 4);
        float* dst = Qs + tok * APITCH + part * 4;
        dst[0] = tf32f(q4.x * SCALE); dst[1] = tf32f(q4.y * SCALE);
        dst[2] = tf32f(q4.z * SCALE); dst[3] = tf32f(q4.w * SCALE);
    }
    // store K/V tile 0 into buffer 0
#pragma unroll
    for (int i = 0; i < 2; i++) {
        int f = tid + i * 256;
        int tok = f >> 3, part = f & 7;
        float* kd = Ks + tok * APITCH + part * 4;
        kd[0] = tf32f(kf[i].x); kd[1] = tf32f(kf[i].y);
        kd[2] = tf32f(kf[i].z); kd[3] = tf32f(kf[i].w);
        float* vd = Vt + tok;
        vd[(part * 4 + 0) * VPITCH] = tf32f(vf[i].x);
        vd[(part * 4 + 1) * VPITCH] = tf32f(vf[i].y);
        vd[(part * 4 + 2) * VPITCH] = tf32f(vf[i].z);
        vd[(part * 4 + 3) * VPITCH] = tf32f(vf[i].w);
    }
    __syncthreads();

    // Q fragments (held in registers for the whole loop)
    uint32_t qa[4][4];
    {
        const uint32_t* Qu = (const uint32_t*)Qs;
        int r0 = wid * 16 + g;
#pragma unroll
        for (int c = 0; c < 4; c++) {
            qa[c][0] = Qu[r0 * APITCH + c * 8 + tg];
            qa[c][1] = Qu[(r0 + 8) * APITCH + c * 8 + tg];
            qa[c][2] = Qu[r0 * APITCH + c * 8 + tg + 4];
            qa[c][3] = Qu[(r0 + 8) * APITCH + c * 8 + tg + 4];
        }
    }

    float oacc[4][4];
#pragma unroll
    for (int nd = 0; nd < 4; nd++)
#pragma unroll
        for (int r = 0; r < 4; r++) oacc[nd][r] = 0.f;
    float m0 = -1e30f, m1 = -1e30f, l0 = 0.f, l1 = 0.f;

    const int qrow_grp = qt * 2 + (wid >= 4 ? 1 : 0);  // q/64 for both rows
    const int qw0 = (wid * 16 + g) & 63;
    const int qw1 = (wid * 16 + g + 8) & 63;

    for (int kt = 0; kt < 8; kt++) {
        int buf = kt & 1;
        if (kt < 7) {
#pragma unroll
            for (int i = 0; i < 2; i++) {
                int f = tid + i * 256;
                int tok = f >> 3, part = f & 7;
                const float* row = base + (size_t)((kt + 1) * 64 + tok) * 576 + hh * HD + part * 4;
                kf[i] = *(const float4*)(row + EMB);
                vf[i] = *(const float4*)(row + 2 * EMB);
            }
        }

        // ---- S = Q K^T (16x64 per warp) ----
        float sc[8][4];
#pragma unroll
        for (int n = 0; n < 8; n++)
#pragma unroll
            for (int r = 0; r < 4; r++) sc[n][r] = 0.f;
        {
            const uint32_t* Ku = (const uint32_t*)(Ks + buf * KS_F);
#pragma unroll
            for (int c = 0; c < 4; c++) {
#pragma unroll
                for (int n = 0; n < 8; n++) {
                    uint32_t b0 = Ku[(n * 8 + g) * APITCH + c * 8 + tg];
                    uint32_t b1 = Ku[(n * 8 + g) * APITCH + c * 8 + tg + 4];
                    mma_tf32(sc[n], qa[c], b0, b1);
                }
            }
        }

        // ---- mask ----
        if (local) {
            int dr = qrow_grp - kt;
            if (dr <= 3 && dr >= -3) {
#pragma unroll
                for (int n = 0; n < 8; n++) {
#pragma unroll
                    for (int j = 0; j < 2; j++) {
                        int col = n * 8 + 2 * tg + j;
                        int d0 = qw0 - col, d1 = qw1 - col;
                        if (d0 <= 5 && d0 >= -5) sc[n][j] = -1e30f;
                        if (d1 <= 5 && d1 >= -5) sc[n][2 + j] = -1e30f;
                    }
                }
            }
        }

        // ---- online softmax ----
        float tm0 = sc[0][0], tm1 = sc[0][2];
#pragma unroll
        for (int n = 0; n < 8; n++) {
            tm0 = fmaxf(tm0, fmaxf(sc[n][0], sc[n][1]));
            tm1 = fmaxf(tm1, fmaxf(sc[n][2], sc[n][3]));
        }
        tm0 = fmaxf(tm0, __shfl_xor_sync(0xffffffffu, tm0, 1));
        tm0 = fmaxf(tm0, __shfl_xor_sync(0xffffffffu, tm0, 2));
        tm1 = fmaxf(tm1, __shfl_xor_sync(0xffffffffu, tm1, 1));
        tm1 = fmaxf(tm1, __shfl_xor_sync(0xffffffffu, tm1, 2));
        float nm0 = fmaxf(m0, tm0), nm1 = fmaxf(m1, tm1);
        float f0 = __expf(m0 - nm0), f1 = __expf(m1 - nm1);
        l0 *= f0; l1 *= f1;
#pragma unroll
        for (int nd = 0; nd < 4; nd++) {
            oacc[nd][0] *= f0; oacc[nd][1] *= f0;
            oacc[nd][2] *= f1; oacc[nd][3] *= f1;
        }
        uint32_t* Pw = (uint32_t*)(Pb + wid * PB_F);
#pragma unroll
        for (int n = 0; n < 8; n++) {
            float p0 = __expf(sc[n][0] - nm0);
            float p1 = __expf(sc[n][1] - nm0);
            float p2 = __expf(sc[n][2] - nm1);
            float p3 = __expf(sc[n][3] - nm1);
            l0 += p0 + p1; l1 += p2 + p3;
            int c0 = n * 8 + 2 * tg;
            Pw[g * PPITCH + c0]       = to_tf32(p0);
            Pw[g * PPITCH + c0 + 1]   = to_tf32(p1);
            Pw[(g + 8) * PPITCH + c0]     = to_tf32(p2);
            Pw[(g + 8) * PPITCH + c0 + 1] = to_tf32(p3);
        }
        m0 = nm0; m1 = nm1;
        __syncwarp();

        // ---- O += P V ----
        {
            const uint32_t* Vu = (const uint32_t*)(Vt + buf * VT_F);
#pragma unroll
            for (int c = 0; c < 8; c++) {
                uint32_t pa[4];
                pa[0] = Pw[g * PPITCH + c * 8 + tg];
                pa[1] = Pw[(g + 8) * PPITCH + c * 8 + tg];
                pa[2] = Pw[g * PPITCH + c * 8 + tg + 4];
                pa[3] = Pw[(g + 8) * PPITCH + c * 8 + tg + 4];
#pragma unroll
                for (int nd = 0; nd < 4; nd++) {
                    uint32_t b0 = Vu[(nd * 8 + g) * VPITCH + c * 8 + tg];
                    uint32_t b1 = Vu[(nd * 8 + g) * VPITCH + c * 8 + tg + 4];
                    mma_tf32(oacc[nd], pa, b0, b1);
                }
            }
        }
        __syncwarp();

        if (kt < 7) {
            __syncthreads();
            int nbuf = buf ^ 1;
#pragma unroll
            for (int i = 0; i < 2; i++) {
                int f = tid + i * 256;
                int tok = f >> 3, part = f & 7;
                float* kd = Ks + nbuf * KS_F + tok * APITCH + part * 4;
                kd[0] = tf32f(kf[i].x); kd[1] = tf32f(kf[i].y);
                kd[2] = tf32f(kf[i].z); kd[3] = tf32f(kf[i].w);
                float* vd = Vt + nbuf * VT_F + tok;
                vd[(part * 4 + 0) * VPITCH] = tf32f(vf[i].x);
                vd[(part * 4 + 1) * VPITCH] = tf32f(vf[i].y);
                vd[(part * 4 + 2) * VPITCH] = tf32f(vf[i].z);
                vd[(part * 4 + 3) * VPITCH] = tf32f(vf[i].w);
            }
            __syncthreads();
        }
    }

    // ---- finalize ----
    l0 += __shfl_xor_sync(0xffffffffu, l0, 1);
    l0 += __shfl_xor_sync(0xffffffffu, l0, 2);
    l1 += __shfl_xor_sync(0xffffffffu, l1, 1);
    l1 += __shfl_xor_sync(0xffffffffu, l1, 2);
    float inv0 = 1.f / l0, inv1 = 1.f / l1;
    int r0 = qt * 128 + wid * 16 + g;
    float* o0 = out + (size_t)(b * SEQ + r0) * EMB + hh * HD;
    float* o1 = out + (size_t)(b * SEQ + r0 + 8) * EMB + hh * HD;
#pragma unroll
    for (int nd = 0; nd < 4; nd++) {
        int n = nd * 8 + 2 * tg;
        float2 v0 = { oacc[nd][0] * inv0, oacc[nd][1] * inv0 };
        float2 v1 = { oacc[nd][2] * inv1, oacc[nd][3] * inv1 };
        *(float2*)(o0 + n) = v0;
        *(float2*)(o1 + n) = v1;
    }
}

// ---------------------------------------------------------------
// Merge: conv (3,1) stride (2,1) pad (1,0) + channel LN, fused.
// ---------------------------------------------------------------
__global__ __launch_bounds__(256) void k_merge(
    const float* __restrict__ cw, const float* __restrict__ cb,
    const float* __restrict__ mg, const float* __restrict__ mb,
    float* __restrict__ out) {
    int blk = blockIdx.x;
    int wg = blk & 15;
    int ho = (blk >> 4) & 3;
    int b  = blk >> 6;
    int co = threadIdx.x;
    __shared__ float xs[4][3][EMB];
    __shared__ float red[256];

    for (int idx = co; idx < 4 * 3 * EMB; idx += 256) {
        int g   = idx / (3 * EMB);
        int rem = idx - g * (3 * EMB);
        int kh  = rem / EMB;
        int ci  = rem - kh * EMB;
        int hh  = 2 * ho - 1 + kh;
        int w   = wg * 4 + g;
        float v = 0.f;
        if (hh >= 0 && hh < 8)
            v = g_x[((size_t)b * SEQ + (w * 8 + hh)) * EMB + ci];
        xs[g][kh][ci] = v;
    }
    __syncthreads();

    float bias = cb[co];
    float acc[4] = {bias, bias, bias, bias};
    const float* wp = cw + (size_t)co * (EMB * 3);
    for (int ci = 0; ci < EMB; ci++) {
        float w0 = wp[ci * 3 + 0], w1 = wp[ci * 3 + 1], w2 = wp[ci * 3 + 2];
#pragma unroll
        for (int g = 0; g < 4; g++)
            acc[g] += xs[g][0][ci] * w0 + xs[g][1][ci] * w1 + xs[g][2][ci] * w2;
    }

#pragma unroll
    for (int g = 0; g < 4; g++) {
        __syncthreads();
        red[co] = acc[g];
        __syncthreads();
        for (int s = 128; s > 0; s >>= 1) {
            if (co < s) red[co] += red[co + s];
            __syncthreads();
        }
        float mu = red[0] * (1.f / 256.f);
        __syncthreads();
        float d = acc[g] - mu;
        red[co] = d * d;
        __syncthreads();
        for (int s = 128; s > 0; s >>= 1) {
            if (co < s) red[co] += red[co + s];
            __syncthreads();
        }
        float rstd = rsqrtf(red[0] * (1.f / 256.f) + 1e-5f);
        int w = wg * 4 + g;
        out[(((size_t)b * 256 + co) * 4 + ho) * 64 + w] = d * rstd * mg[co] + mb[co];
    }
}

// ---------------------------------------------------------------
extern "C" void kernel_launch(void* const* d_in, const int* in_sizes, int n_in,
                              void* d_out, int out_size) {
    const float* image = (const float*)d_in[0];
    const float* in_w  = (const float*)d_in[1];
    const float* in_b  = (const float*)d_in[2];
    const float* out_w = (const float*)d_in[3];
    const float* out_b = (const float*)d_in[4];
    const float* ln1_g = (const float*)d_in[5];
    const float* ln1_b = (const float*)d_in[6];
    const float* ln2_g = (const float*)d_in[7];
    const float* ln2_b = (const float*)d_in[8];
    const float* w1    = (const float*)d_in[9];
    const float* b1    = (const float*)d_in[10];
    const float* w2    = (const float*)d_in[11];
    const float* b2    = (const float*)d_in[12];
    const float* convw = (const float*)d_in[13];
    const float* convb = (const float*)d_in[14];
    const float* mlng  = (const float*)d_in[15];
    const float* mlnb  = (const float*)d_in[16];

    float *px, *pxn, *pbig, *pattn;
    cudaGetSymbolAddress((void**)&px,    g_x);
    cudaGetSymbolAddress((void**)&pxn,   g_xn);
    cudaGetSymbolAddress((void**)&pbig,  g_big);
    cudaGetSymbolAddress((void**)&pattn, g_attn);

    cudaFuncSetAttribute(k_gemm_tc<0, 0>, cudaFuncAttributeMaxDynamicSharedMemorySize, GSMEM_BYTES);
    cudaFuncSetAttribute(k_gemm_tc<0, 1>, cudaFuncAttributeMaxDynamicSharedMemorySize, GSMEM_BYTES);
    cudaFuncSetAttribute(k_gemm_tc<1, 0>, cudaFuncAttributeMaxDynamicSharedMemorySize, GSMEM_BYTES);
    cudaFuncSetAttribute(k_attn_tc, cudaFuncAttributeMaxDynamicSharedMemorySize, ATTN_SMEM_B);

    k_tin<<<(BATCH * SEQ * EMB + 255) / 256, 256>>>(image);

    for (int l = 0; l < 6; l++) {
        int local = (l >= 2);  // LOCAL = (F, F, T, T, T, T)
        // xn = LN1(x)
        k_ln192<<<MROWS / 8, 256>>>(px, pxn, ln1_g + l * EMB, ln1_b + l * EMB);
        // qkv = xn @ Wi^T + bi   [32768, 576]
        k_gemm_tc<0, 0><<<dim3(9, MROWS / 128), 256, GSMEM_BYTES>>>(
            pxn, in_w + (size_t)l * 576 * EMB, in_b + l * 576,
            nullptr, pbig, 576, EMB);
        // attn = softmax(qk^T/sqrt(hd) [mask]) @ v
        k_attn_tc<<<dim3(4, NHEAD, BATCH), 256, ATTN_SMEM_B>>>(pbig, pattn, local);
        // x = attn @ Wo^T + bo + xn   (residual uses post-LN xn!)
        k_gemm_tc<0, 1><<<dim3(3, MROWS / 128), 256, GSMEM_BYTES>>>(
            pattn, out_w + (size_t)l * EMB * EMB, out_b + l * EMB,
            pxn, px, EMB, EMB);
        // xn = LN2(x)
        k_ln192<<<MROWS / 8, 256>>>(px, pxn, ln2_g + l * EMB, ln2_b + l * EMB);
        // h = relu(xn @ w1^T + b1)   [32768, 768]
        k_gemm_tc<1, 0><<<dim3(12, MROWS / 128), 256, GSMEM_BYTES>>>(
            pxn, w1 + (size_t)l * 768 * EMB, b1 + l * 768,
            nullptr, pbig, 768, EMB);
        // x = h @ w2^T + b2 + xn     (residual uses post-LN xn!)
        k_gemm_tc<0, 1><<<dim3(3, MROWS / 128), 256, GSMEM_BYTES>>>(
            pbig, w2 + (size_t)l * EMB * 768, b2 + l * EMB,
            pxn, px, EMB, 768);
    }

    k_merge<<<4096, 256>>>(convw, convb, mlng, mlnb, (float*)d_out);
}

// round 5
// speedup vs baseline: 2.3665x; 1.0313x over previous
#include <cuda_runtime.h>
#include <math.h>
#include <stdint.h>

#define BATCH 64
#define SEQ   512
#define EMB   192
#define NHEAD 6
#define HD    32
#define MROWS (BATCH * SEQ)   // 32768

// -------- scratch (device globals; no runtime allocation) --------
__device__ float g_x   [BATCH * SEQ * EMB];   // residual stream
__device__ float g_xn  [BATCH * SEQ * EMB];   // LN output
__device__ float g_big [BATCH * SEQ * 768];   // qkv (576 used) / mlp hidden (768)
__device__ float g_attn[BATCH * SEQ * EMB];   // attention head-merged output

__device__ __forceinline__ uint32_t to_tf32(float v) {
    uint32_t r;
    asm("cvt.rna.tf32.f32 %0, %1;" : "=r"(r) : "f"(v));
    return r;
}
__device__ __forceinline__ float tf32f(float v) {
    return __uint_as_float(to_tf32(v));
}
__device__ __forceinline__ void mma_tf32(float* c, const uint32_t* a,
                                         uint32_t b0, uint32_t b1) {
    asm volatile(
        "mma.sync.aligned.m16n8k8.row.col.f32.tf32.tf32.f32 "
        "{%0,%1,%2,%3}, {%4,%5,%6,%7}, {%8,%9}, {%0,%1,%2,%3};"
        : "+f"(c[0]), "+f"(c[1]), "+f"(c[2]), "+f"(c[3])
        : "r"(a[0]), "r"(a[1]), "r"(a[2]), "r"(a[3]), "r"(b0), "r"(b1));
}
__device__ __forceinline__ void cp16g(float* dst, const float* src) {
    uint32_t d;
    asm("{ .reg .u64 t; cvta.to.shared.u64 t, %1; cvt.u32.u64 %0, t; }"
        : "=r"(d) : "l"(dst));
    asm volatile("cp.async.cg.shared.global [%0], [%1], 16;" :: "r"(d), "l"(src));
}

// ---------------------------------------------------------------
// input transpose: image [B, C, H, W] -> x [B, S=W*H, C], token t = w*8 + h
// ---------------------------------------------------------------
__global__ void k_tin(const float* __restrict__ img) {
    int idx = blockIdx.x * 256 + threadIdx.x;
    if (idx >= BATCH * SEQ * EMB) return;
    int c = idx % EMB;
    int t = (idx / EMB) & (SEQ - 1);
    int b = idx / (EMB * SEQ);
    int w = t >> 3, h = t & 7;
    g_x[idx] = img[(((size_t)b * EMB + c) * 8 + h) * 64 + w];
}

// ---------------------------------------------------------------
// LayerNorm over E=192. One warp per row, 6 elems per lane.
// ---------------------------------------------------------------
__global__ __launch_bounds__(256) void k_ln192(
    const float* __restrict__ in, float* __restrict__ out,
    const float* __restrict__ gam, const float* __restrict__ bet) {
    int row  = blockIdx.x * 8 + (threadIdx.x >> 5);
    int lane = threadIdx.x & 31;
    const float* p = in + (size_t)row * EMB;
    float v[6];
    float s = 0.f;
#pragma unroll
    for (int i = 0; i < 6; i++) { v[i] = p[lane + 32 * i]; s += v[i]; }
#pragma unroll
    for (int o = 16; o; o >>= 1) s += __shfl_xor_sync(0xffffffffu, s, o);
    float mu = s * (1.f / 192.f);
    float q = 0.f;
#pragma unroll
    for (int i = 0; i < 6; i++) { float d = v[i] - mu; q += d * d; }
#pragma unroll
    for (int o = 16; o; o >>= 1) q += __shfl_xor_sync(0xffffffffu, q, o);
    float rstd = rsqrtf(q * (1.f / 192.f) + 1e-5f);
    float* op = out + (size_t)row * EMB;
#pragma unroll
    for (int i = 0; i < 6; i++) {
        int c = lane + 32 * i;
        op[c] = (v[i] - mu) * rstd * gam[c] + bet[c];
    }
}

// ---------------------------------------------------------------
// tf32 tensor-core GEMM (legacy mma.sync path):
// C[M,Ntot] = A[M,K] @ W[Ntot,K]^T + bias (+ReLU) (+residual)
// BM=128, BN=64, BK=32; 256 threads = 8 warps (4x2); warp tile 32x32.
// K templated (full unroll), 3-stage cp.async ring, raw-f32 tf32 feed.
// ---------------------------------------------------------------
#define PITCH 36
#define STAGE_F (128 * PITCH + 64 * PITCH)   // 6912 floats = 27648 B
#define GSMEM_BYTES (3 * STAGE_F * 4)        // 82944 B

template <int RELU, int RES, int KT>
__global__ __launch_bounds__(256, 2) void k_gemm_tc(
    const float* __restrict__ A, const float* __restrict__ W,
    const float* __restrict__ bias, const float* __restrict__ R,
    float* __restrict__ C, int Ntot) {
    extern __shared__ float sh[];
    const int K = KT * 32;

    const int bm = blockIdx.y * 128;
    const int bn = blockIdx.x * 64;
    const int tid = threadIdx.x;
    const int wid = tid >> 5;
    const int lane = tid & 31;
    const int wm = wid >> 1;
    const int wn = wid & 1;
    const int g  = lane >> 2;
    const int tg = lane & 3;

    auto load_stage = [&](int kt, int s) {
        float* as = sh + s * STAGE_F;
        float* bs = as + 128 * PITCH;
        const float* Ab = A + (size_t)bm * K + kt * 32;
        const float* Wb = W + (size_t)bn * K + kt * 32;
#pragma unroll
        for (int i = 0; i < 4; i++) {
            int id = tid + i * 256;
            int r = id >> 3, c = id & 7;
            cp16g(as + r * PITCH + c * 4, Ab + (size_t)r * K + c * 4);
        }
#pragma unroll
        for (int i = 0; i < 2; i++) {
            int id = tid + i * 256;
            int r = id >> 3, c = id & 7;
            cp16g(bs + r * PITCH + c * 4, Wb + (size_t)r * K + c * 4);
        }
        asm volatile("cp.async.commit_group;" ::: "memory");
    };

    float acc[2][4][4];
#pragma unroll
    for (int mm = 0; mm < 2; mm++)
#pragma unroll
        for (int nn = 0; nn < 4; nn++)
#pragma unroll
            for (int r = 0; r < 4; r++) acc[mm][nn][r] = 0.f;

    load_stage(0, 0);
    if (KT > 1) load_stage(1, 1);

#pragma unroll
    for (int kt = 0; kt < KT; kt++) {
        const int s = kt % 3;
        __syncthreads();   // all warps past compute of iter kt-1 (its slot is reused by kt+2)
        if (kt + 2 < KT) load_stage(kt + 2, (kt + 2) % 3);
        if (kt + 2 < KT) {
            asm volatile("cp.async.wait_group 2;" ::: "memory");
        } else if (kt + 1 < KT) {
            asm volatile("cp.async.wait_group 1;" ::: "memory");
        } else {
            asm volatile("cp.async.wait_group 0;" ::: "memory");
        }
        __syncthreads();

        const uint32_t* as = (const uint32_t*)(sh + s * STAGE_F);
        const uint32_t* bs = as + 128 * PITCH;
#pragma unroll
        for (int ks = 0; ks < 4; ks++) {
            int k0 = ks * 8;
            uint32_t a[2][4], b[4][2];
#pragma unroll
            for (int mm = 0; mm < 2; mm++) {
                int r0 = wm * 32 + mm * 16 + g;
                a[mm][0] = as[r0 * PITCH + k0 + tg];
                a[mm][1] = as[(r0 + 8) * PITCH + k0 + tg];
                a[mm][2] = as[r0 * PITCH + k0 + tg + 4];
                a[mm][3] = as[(r0 + 8) * PITCH + k0 + tg + 4];
            }
#pragma unroll
            for (int nn = 0; nn < 4; nn++) {
                int n0 = wn * 32 + nn * 8 + g;
                b[nn][0] = bs[n0 * PITCH + k0 + tg];
                b[nn][1] = bs[n0 * PITCH + k0 + tg + 4];
            }
#pragma unroll
            for (int mm = 0; mm < 2; mm++)
#pragma unroll
                for (int nn = 0; nn < 4; nn++)
                    mma_tf32(acc[mm][nn], a[mm], b[nn][0], b[nn][1]);
        }
    }

#pragma unroll
    for (int mm = 0; mm < 2; mm++) {
#pragma unroll
        for (int half = 0; half < 2; half++) {
            int m = bm + wm * 32 + mm * 16 + g + half * 8;
            float* crow = C + (size_t)m * Ntot + bn;
            const float* rrow = RES ? (R + (size_t)m * Ntot + bn) : (const float*)0;
#pragma unroll
            for (int nn = 0; nn < 4; nn++) {
                int n = wn * 32 + nn * 8 + 2 * tg;
                float2 v;
                v.x = acc[mm][nn][half * 2 + 0] + bias[bn + n];
                v.y = acc[mm][nn][half * 2 + 1] + bias[bn + n + 1];
                if (RELU) { v.x = fmaxf(v.x, 0.f); v.y = fmaxf(v.y, 0.f); }
                if (RES) {
                    float2 r2 = *(const float2*)(rrow + n);
                    v.x += r2.x; v.y += r2.y;
                }
                *(float2*)(crow + n) = v;
            }
        }
    }
}

// ---------------------------------------------------------------
// Tensor-core flash attention (tf32 mma.sync).
// Block: (qtile 128, head, batch); 256 thr = 8 warps; warp = 16 q-rows.
// qkv [B,S,576]; mask (local): |q/64 - k/64|<=3 && |q%64 - k%64|<=5 -> -inf
// ---------------------------------------------------------------
#define APITCH 36
#define VPITCH 68
#define PPITCH 68
#define QS_F   (128 * APITCH)
#define KS_F   (64 * APITCH)
#define VT_F   (32 * VPITCH)
#define PB_F   (16 * PPITCH)
#define ATTN_SMEM_F (QS_F + 2 * KS_F + 2 * VT_F + 8 * PB_F)
#define ATTN_SMEM_B (ATTN_SMEM_F * 4)

__global__ __launch_bounds__(256, 2) void k_attn_tc(
    const float* __restrict__ qkv, float* __restrict__ out, int local) {
    extern __shared__ float sm[];
    float* Qs = sm;
    float* Ks = Qs + QS_F;
    float* Vt = Ks + 2 * KS_F;
    float* Pb = Vt + 2 * VT_F;

    const int qt = blockIdx.x, hh = blockIdx.y, b = blockIdx.z;
    const int tid = threadIdx.x;
    const int wid = tid >> 5;
    const int lane = tid & 31;
    const int g = lane >> 2, tg = lane & 3;
    const float* base = qkv + (size_t)b * SEQ * 576;
    const float SCALE = 0.17677669529663687f; // 1/sqrt(32)

    float4 kf[2], vf[2];
#pragma unroll
    for (int i = 0; i < 2; i++) {
        int f = tid + i * 256;
        int tok = f >> 3, part = f & 7;
        const float* row = base + (size_t)tok * 576 + hh * HD + part * 4;
        kf[i] = *(const float4*)(row + EMB);
        vf[i] = *(const float4*)(row + 2 * EMB);
    }
#pragma unroll
    for (int i = 0; i < 4; i++) {
        int f = tid + i * 256;
        int tok = f >> 3, part = f & 7;
        float4 q4 = *(const float4*)(base + (size_t)(qt * 128 + tok) * 576 + hh * HD + part * 4);
        float* dst = Qs + tok * APITCH + part * 4;
        dst[0] = tf32f(q4.x * SCALE); dst[1] = tf32f(q4.y * SCALE);
        dst[2] = tf32f(q4.z * SCALE); dst[3] = tf32f(q4.w * SCALE);
    }
#pragma unroll
    for (int i = 0; i < 2; i++) {
        int f = tid + i * 256;
        int tok = f >> 3, part = f & 7;
        float* kd = Ks + tok * APITCH + part * 4;
        kd[0] = tf32f(kf[i].x); kd[1] = tf32f(kf[i].y);
        kd[2] = tf32f(kf[i].z); kd[3] = tf32f(kf[i].w);
        float* vd = Vt + tok;
        vd[(part * 4 + 0) * VPITCH] = tf32f(vf[i].x);
        vd[(part * 4 + 1) * VPITCH] = tf32f(vf[i].y);
        vd[(part * 4 + 2) * VPITCH] = tf32f(vf[i].z);
        vd[(part * 4 + 3) * VPITCH] = tf32f(vf[i].w);
    }
    __syncthreads();

    uint32_t qa[4][4];
    {
        const uint32_t* Qu = (const uint32_t*)Qs;
        int r0 = wid * 16 + g;
#pragma unroll
        for (int c = 0; c < 4; c++) {
            qa[c][0] = Qu[r0 * APITCH + c * 8 + tg];
            qa[c][1] = Qu[(r0 + 8) * APITCH + c * 8 + tg];
            qa[c][2] = Qu[r0 * APITCH + c * 8 + tg + 4];
            qa[c][3] = Qu[(r0 + 8) * APITCH + c * 8 + tg + 4];
        }
    }

    float oacc[4][4];
#pragma unroll
    for (int nd = 0; nd < 4; nd++)
#pragma unroll
        for (int r = 0; r < 4; r++) oacc[nd][r] = 0.f;
    float m0 = -1e30f, m1 = -1e30f, l0 = 0.f, l1 = 0.f;

    const int qrow_grp = qt * 2 + (wid >= 4 ? 1 : 0);
    const int qw0 = (wid * 16 + g) & 63;
    const int qw1 = (wid * 16 + g + 8) & 63;

    for (int kt = 0; kt < 8; kt++) {
        int buf = kt & 1;
        if (kt < 7) {
#pragma unroll
            for (int i = 0; i < 2; i++) {
                int f = tid + i * 256;
                int tok = f >> 3, part = f & 7;
                const float* row = base + (size_t)((kt + 1) * 64 + tok) * 576 + hh * HD + part * 4;
                kf[i] = *(const float4*)(row + EMB);
                vf[i] = *(const float4*)(row + 2 * EMB);
            }
        }

        float sc[8][4];
#pragma unroll
        for (int n = 0; n < 8; n++)
#pragma unroll
            for (int r = 0; r < 4; r++) sc[n][r] = 0.f;
        {
            const uint32_t* Ku = (const uint32_t*)(Ks + buf * KS_F);
#pragma unroll
            for (int c = 0; c < 4; c++) {
#pragma unroll
                for (int n = 0; n < 8; n++) {
                    uint32_t b0 = Ku[(n * 8 + g) * APITCH + c * 8 + tg];
                    uint32_t b1 = Ku[(n * 8 + g) * APITCH + c * 8 + tg + 4];
                    mma_tf32(sc[n], qa[c], b0, b1);
                }
            }
        }

        if (local) {
            int dr = qrow_grp - kt;
            if (dr <= 3 && dr >= -3) {
#pragma unroll
                for (int n = 0; n < 8; n++) {
#pragma unroll
                    for (int j = 0; j < 2; j++) {
                        int col = n * 8 + 2 * tg + j;
                        int d0 = qw0 - col, d1 = qw1 - col;
                        if (d0 <= 5 && d0 >= -5) sc[n][j] = -1e30f;
                        if (d1 <= 5 && d1 >= -5) sc[n][2 + j] = -1e30f;
                    }
                }
            }
        }

        float tm0 = sc[0][0], tm1 = sc[0][2];
#pragma unroll
        for (int n = 0; n < 8; n++) {
            tm0 = fmaxf(tm0, fmaxf(sc[n][0], sc[n][1]));
            tm1 = fmaxf(tm1, fmaxf(sc[n][2], sc[n][3]));
        }
        tm0 = fmaxf(tm0, __shfl_xor_sync(0xffffffffu, tm0, 1));
        tm0 = fmaxf(tm0, __shfl_xor_sync(0xffffffffu, tm0, 2));
        tm1 = fmaxf(tm1, __shfl_xor_sync(0xffffffffu, tm1, 1));
        tm1 = fmaxf(tm1, __shfl_xor_sync(0xffffffffu, tm1, 2));
        float nm0 = fmaxf(m0, tm0), nm1 = fmaxf(m1, tm1);
        float f0 = __expf(m0 - nm0), f1 = __expf(m1 - nm1);
        l0 *= f0; l1 *= f1;
#pragma unroll
        for (int nd = 0; nd < 4; nd++) {
            oacc[nd][0] *= f0; oacc[nd][1] *= f0;
            oacc[nd][2] *= f1; oacc[nd][3] *= f1;
        }
        uint32_t* Pw = (uint32_t*)(Pb + wid * PB_F);
#pragma unroll
        for (int n = 0; n < 8; n++) {
            float p0 = __expf(sc[n][0] - nm0);
            float p1 = __expf(sc[n][1] - nm0);
            float p2 = __expf(sc[n][2] - nm1);
            float p3 = __expf(sc[n][3] - nm1);
            l0 += p0 + p1; l1 += p2 + p3;
            int c0 = n * 8 + 2 * tg;
            Pw[g * PPITCH + c0]       = to_tf32(p0);
            Pw[g * PPITCH + c0 + 1]   = to_tf32(p1);
            Pw[(g + 8) * PPITCH + c0]     = to_tf32(p2);
            Pw[(g + 8) * PPITCH + c0 + 1] = to_tf32(p3);
        }
        m0 = nm0; m1 = nm1;
        __syncwarp();

        {
            const uint32_t* Vu = (const uint32_t*)(Vt + buf * VT_F);
#pragma unroll
            for (int c = 0; c < 8; c++) {
                uint32_t pa[4];
                pa[0] = Pw[g * PPITCH + c * 8 + tg];
                pa[1] = Pw[(g + 8) * PPITCH + c * 8 + tg];
                pa[2] = Pw[g * PPITCH + c * 8 + tg + 4];
                pa[3] = Pw[(g + 8) * PPITCH + c * 8 + tg + 4];
#pragma unroll
                for (int nd = 0; nd < 4; nd++) {
                    uint32_t b0 = Vu[(nd * 8 + g) * VPITCH + c * 8 + tg];
                    uint32_t b1 = Vu[(nd * 8 + g) * VPITCH + c * 8 + tg + 4];
                    mma_tf32(oacc[nd], pa, b0, b1);
                }
            }
        }
        __syncwarp();

        if (kt < 7) {
            __syncthreads();
            int nbuf = buf ^ 1;
#pragma unroll
            for (int i = 0; i < 2; i++) {
                int f = tid + i * 256;
                int tok = f >> 3, part = f & 7;
                float* kd = Ks + nbuf * KS_F + tok * APITCH + part * 4;
                kd[0] = tf32f(kf[i].x); kd[1] = tf32f(kf[i].y);
                kd[2] = tf32f(kf[i].z); kd[3] = tf32f(kf[i].w);
                float* vd = Vt + nbuf * VT_F + tok;
                vd[(part * 4 + 0) * VPITCH] = tf32f(vf[i].x);
                vd[(part * 4 + 1) * VPITCH] = tf32f(vf[i].y);
                vd[(part * 4 + 2) * VPITCH] = tf32f(vf[i].z);
                vd[(part * 4 + 3) * VPITCH] = tf32f(vf[i].w);
            }
            __syncthreads();
        }
    }

    l0 += __shfl_xor_sync(0xffffffffu, l0, 1);
    l0 += __shfl_xor_sync(0xffffffffu, l0, 2);
    l1 += __shfl_xor_sync(0xffffffffu, l1, 1);
    l1 += __shfl_xor_sync(0xffffffffu, l1, 2);
    float inv0 = 1.f / l0, inv1 = 1.f / l1;
    int r0 = qt * 128 + wid * 16 + g;
    float* o0 = out + (size_t)(b * SEQ + r0) * EMB + hh * HD;
    float* o1 = out + (size_t)(b * SEQ + r0 + 8) * EMB + hh * HD;
#pragma unroll
    for (int nd = 0; nd < 4; nd++) {
        int n = nd * 8 + 2 * tg;
        float2 v0 = { oacc[nd][0] * inv0, oacc[nd][1] * inv0 };
        float2 v1 = { oacc[nd][2] * inv1, oacc[nd][3] * inv1 };
        *(float2*)(o0 + n) = v0;
        *(float2*)(o1 + n) = v1;
    }
}

// ---------------------------------------------------------------
// Merge: conv (3,1) stride (2,1) pad (1,0) + channel LN, fused.
// ---------------------------------------------------------------
__global__ __launch_bounds__(256) void k_merge(
    const float* __restrict__ cw, const float* __restrict__ cb,
    const float* __restrict__ mg, const float* __restrict__ mb,
    float* __restrict__ out) {
    int blk = blockIdx.x;
    int wg = blk & 15;
    int ho = (blk >> 4) & 3;
    int b  = blk >> 6;
    int co = threadIdx.x;
    __shared__ float xs[4][3][EMB];
    __shared__ float red[256];

    for (int idx = co; idx < 4 * 3 * EMB; idx += 256) {
        int g   = idx / (3 * EMB);
        int rem = idx - g * (3 * EMB);
        int kh  = rem / EMB;
        int ci  = rem - kh * EMB;
        int hh  = 2 * ho - 1 + kh;
        int w   = wg * 4 + g;
        float v = 0.f;
        if (hh >= 0 && hh < 8)
            v = g_x[((size_t)b * SEQ + (w * 8 + hh)) * EMB + ci];
        xs[g][kh][ci] = v;
    }
    __syncthreads();

    float bias = cb[co];
    float acc[4] = {bias, bias, bias, bias};
    const float* wp = cw + (size_t)co * (EMB * 3);
    for (int ci = 0; ci < EMB; ci++) {
        float w0 = wp[ci * 3 + 0], w1 = wp[ci * 3 + 1], w2 = wp[ci * 3 + 2];
#pragma unroll
        for (int g = 0; g < 4; g++)
            acc[g] += xs[g][0][ci] * w0 + xs[g][1][ci] * w1 + xs[g][2][ci] * w2;
    }

#pragma unroll
    for (int g = 0; g < 4; g++) {
        __syncthreads();
        red[co] = acc[g];
        __syncthreads();
        for (int s = 128; s > 0; s >>= 1) {
            if (co < s) red[co] += red[co + s];
            __syncthreads();
        }
        float mu = red[0] * (1.f / 256.f);
        __syncthreads();
        float d = acc[g] - mu;
        red[co] = d * d;
        __syncthreads();
        for (int s = 128; s > 0; s >>= 1) {
            if (co < s) red[co] += red[co + s];
            __syncthreads();
        }
        float rstd = rsqrtf(red[0] * (1.f / 256.f) + 1e-5f);
        int w = wg * 4 + g;
        out[(((size_t)b * 256 + co) * 4 + ho) * 64 + w] = d * rstd * mg[co] + mb[co];
    }
}

// ---------------------------------------------------------------
extern "C" void kernel_launch(void* const* d_in, const int* in_sizes, int n_in,
                              void* d_out, int out_size) {
    const float* image = (const float*)d_in[0];
    const float* in_w  = (const float*)d_in[1];
    const float* in_b  = (const float*)d_in[2];
    const float* out_w = (const float*)d_in[3];
    const float* out_b = (const float*)d_in[4];
    const float* ln1_g = (const float*)d_in[5];
    const float* ln1_b = (const float*)d_in[6];
    const float* ln2_g = (const float*)d_in[7];
    const float* ln2_b = (const float*)d_in[8];
    const float* w1    = (const float*)d_in[9];
    const float* b1    = (const float*)d_in[10];
    const float* w2    = (const float*)d_in[11];
    const float* b2    = (const float*)d_in[12];
    const float* convw = (const float*)d_in[13];
    const float* convb = (const float*)d_in[14];
    const float* mlng  = (const float*)d_in[15];
    const float* mlnb  = (const float*)d_in[16];

    float *px, *pxn, *pbig, *pattn;
    cudaGetSymbolAddress((void**)&px,    g_x);
    cudaGetSymbolAddress((void**)&pxn,   g_xn);
    cudaGetSymbolAddress((void**)&pbig,  g_big);
    cudaGetSymbolAddress((void**)&pattn, g_attn);

    cudaFuncSetAttribute(k_gemm_tc<0, 0, 6>,  cudaFuncAttributeMaxDynamicSharedMemorySize, GSMEM_BYTES);
    cudaFuncSetAttribute(k_gemm_tc<0, 1, 6>,  cudaFuncAttributeMaxDynamicSharedMemorySize, GSMEM_BYTES);
    cudaFuncSetAttribute(k_gemm_tc<1, 0, 6>,  cudaFuncAttributeMaxDynamicSharedMemorySize, GSMEM_BYTES);
    cudaFuncSetAttribute(k_gemm_tc<0, 1, 24>, cudaFuncAttributeMaxDynamicSharedMemorySize, GSMEM_BYTES);
    cudaFuncSetAttribute(k_attn_tc, cudaFuncAttributeMaxDynamicSharedMemorySize, ATTN_SMEM_B);

    k_tin<<<(BATCH * SEQ * EMB + 255) / 256, 256>>>(image);

    for (int l = 0; l < 6; l++) {
        int local = (l >= 2);  // LOCAL = (F, F, T, T, T, T)
        // xn = LN1(x)
        k_ln192<<<MROWS / 8, 256>>>(px, pxn, ln1_g + l * EMB, ln1_b + l * EMB);
        // qkv = xn @ Wi^T + bi   [32768, 576]
        k_gemm_tc<0, 0, 6><<<dim3(9, MROWS / 128), 256, GSMEM_BYTES>>>(
            pxn, in_w + (size_t)l * 576 * EMB, in_b + l * 576,
            nullptr, pbig, 576);
        // attn = softmax(qk^T/sqrt(hd) [mask]) @ v
        k_attn_tc<<<dim3(4, NHEAD, BATCH), 256, ATTN_SMEM_B>>>(pbig, pattn, local);
        // x = attn @ Wo^T + bo + xn   (residual uses post-LN xn!)
        k_gemm_tc<0, 1, 6><<<dim3(3, MROWS / 128), 256, GSMEM_BYTES>>>(
            pattn, out_w + (size_t)l * EMB * EMB, out_b + l * EMB,
            pxn, px, EMB);
        // xn = LN2(x)
        k_ln192<<<MROWS / 8, 256>>>(px, pxn, ln2_g + l * EMB, ln2_b + l * EMB);
        // h = relu(xn @ w1^T + b1)   [32768, 768]
        k_gemm_tc<1, 0, 6><<<dim3(12, MROWS / 128), 256, GSMEM_BYTES>>>(
            pxn, w1 + (size_t)l * 768 * EMB, b1 + l * 768,
            nullptr, pbig, 768);
        // x = h @ w2^T + b2 + xn     (residual uses post-LN xn!)
        k_gemm_tc<0, 1, 24><<<dim3(3, MROWS / 128), 256, GSMEM_BYTES>>>(
            pbig, w2 + (size_t)l * EMB * 768, b2 + l * EMB,
            pxn, px, EMB);
    }

    k_merge<<<4096, 256>>>(convw, convb, mlng, mlnb, (float*)d_out);
}